// round 14
// baseline (speedup 1.0000x reference)
#include <cuda_runtime.h>
#include <cuda_bf16.h>
#include <math.h>
#include <stdint.h>

// Problem constants
#define NV   20000
#define ME   5000
#define EI   160000
#define CDIM 1024
#define HIDD 512
#define NB   3

// ---------------- device scratch (static, no allocation) ----------------
__device__ __align__(16) float g_bufA[NB][(size_t)NV * HIDD];
__device__ __align__(16) float g_bufC[NB][(size_t)NV * CDIM];
__device__ __align__(16) float g_bufD[NB][(size_t)NV * CDIM];
__device__ __align__(16) float g_Y[NB][(size_t)ME * CDIM];
__device__ __align__(16) float g_ybuf[NB][(size_t)ME * CDIM];
__device__ float g_alpha[NB][ME];
__device__ float g_vm[NB][NV];
__device__ float g_vwinv[NB][NV];
__device__ float g_logits[NB][NV];

__device__ int g_degE[NB][ME], g_eoff[NB][ME + 1], g_ecur[NB][ME];
__device__ int g_degV[NB][NV], g_voff[NB][NV + 1], g_vcur[NB][NV];
__device__ int g_elist[NB][EI];
__device__ int g_vlist[NB][EI];

__device__ float g_gvec[NB][CDIM];
__device__ float g_gout[NB][CDIM];
__device__ unsigned g_menc[NB];
__device__ float g_S[NB];

__device__ __align__(16) __nv_bfloat16 g_Acthi[NB][(size_t)NV * CDIM];
__device__ __align__(16) __nv_bfloat16 g_Actlo[NB][(size_t)NV * CDIM];

// shared weights
__device__ float g_gcat[6 * CDIM];
__device__ float g_gcatn[6 * CDIM];
__device__ __align__(16) __nv_bfloat16 g_Wt0hi[512 * 1024], g_Wt0lo[512 * 1024];
__device__ __align__(16) __nv_bfloat16 g_Wt1hi[1024 * 512], g_Wt1lo[1024 * 512];
__device__ __align__(16) __nv_bfloat16 g_Wabhi[512 * 1024];   // interleaved Wa/Wb rows

// ---------------- helpers ----------------
__device__ __forceinline__ uint32_t smem_u32(const void* p) {
    uint32_t a;
    asm("{ .reg .u64 t; cvta.to.shared.u64 t, %1; cvt.u32.u64 %0, t; }"
        : "=r"(a) : "l"(p));
    return a;
}

__device__ __forceinline__ void cp_cg(uint32_t s, const void* g, int bytes) {
    asm volatile("cp.async.cg.shared.global [%0], [%1], 16, %2;"
                 :: "r"(s), "l"(g), "r"(bytes) : "memory");
}

__device__ __forceinline__ void ldsm4(uint32_t* r, uint32_t addr) {
    asm volatile("ldmatrix.sync.aligned.m8n8.x4.shared.b16 {%0,%1,%2,%3}, [%4];"
                 : "=r"(r[0]), "=r"(r[1]), "=r"(r[2]), "=r"(r[3]) : "r"(addr));
}

__device__ __forceinline__ void mma16816(float* d, const uint32_t* a, const uint32_t* b) {
    asm volatile(
        "mma.sync.aligned.m16n8k16.row.col.f32.bf16.bf16.f32 "
        "{%0,%1,%2,%3}, {%4,%5,%6,%7}, {%8,%9}, {%0,%1,%2,%3};"
        : "+f"(d[0]), "+f"(d[1]), "+f"(d[2]), "+f"(d[3])
        : "r"(a[0]), "r"(a[1]), "r"(a[2]), "r"(a[3]), "r"(b[0]), "r"(b[1]));
}

__device__ __forceinline__ unsigned fenc(float f) {
    unsigned u = __float_as_uint(f);
    return (u & 0x80000000u) ? ~u : (u | 0x80000000u);
}
__device__ __forceinline__ float fdec(unsigned e) {
    unsigned u = (e & 0x80000000u) ? (e & 0x7FFFFFFFu) : ~e;
    return __uint_as_float(u);
}

// ---------------- fp32 -> bf16 hi/lo split ----------------
__global__ void __launch_bounds__(256)
k_split(const float* __restrict__ src, __nv_bfloat16* __restrict__ hi,
        __nv_bfloat16* __restrict__ lo, int n4) {
    int i = blockIdx.x * blockDim.x + threadIdx.x;
    if (i >= n4) return;
    float4 v = ((const float4*)src)[i];
    __nv_bfloat16 h[4], l[4];
    float x[4] = {v.x, v.y, v.z, v.w};
#pragma unroll
    for (int j = 0; j < 4; ++j) {
        h[j] = __float2bfloat16(x[j]);
        l[j] = __float2bfloat16(x[j] - __bfloat162float(h[j]));
    }
    ((__nv_bfloat162*)hi)[2 * i]     = __nv_bfloat162(h[0], h[1]);
    ((__nv_bfloat162*)hi)[2 * i + 1] = __nv_bfloat162(h[2], h[3]);
    ((__nv_bfloat162*)lo)[2 * i]     = __nv_bfloat162(l[0], l[1]);
    ((__nv_bfloat162*)lo)[2 * i + 1] = __nv_bfloat162(l[2], l[3]);
}

// interleave Wa/Wb rows: out row 2j = Wa[j], row 2j+1 = Wb[j]; bf16 hi only
__global__ void __launch_bounds__(256)
k_split_inter(const float* __restrict__ Wa, const float* __restrict__ Wb,
              __nv_bfloat16* __restrict__ hi) {
    int i = blockIdx.x * 256 + threadIdx.x;          // float4 index, 512*256 total
    if (i >= 512 * 256) return;
    int row = i >> 8, c4 = i & 255;
    const float* src = ((row & 1) ? Wb : Wa) + (size_t)(row >> 1) * 1024 + c4 * 4;
    float4 v = *(const float4*)src;
    __nv_bfloat162* ph = (__nv_bfloat162*)(hi + (size_t)row * 1024 + c4 * 4);
    ph[0] = __nv_bfloat162(__float2bfloat16(v.x), __float2bfloat16(v.y));
    ph[1] = __nv_bfloat162(__float2bfloat16(v.z), __float2bfloat16(v.w));
}

// ---------------- bf16 tensor-core GEMM ----------------
// k_mma_gemm3: 3-pass Ootomo split, writes C = A@B^T + bias. 128 regs, 2 CTAs/SM.
__global__ void __launch_bounds__(256, 2)
k_mma_gemm3(const __nv_bfloat16* __restrict__ Ahi, const __nv_bfloat16* __restrict__ Alo,
            const __nv_bfloat16* __restrict__ Bhi, const __nv_bfloat16* __restrict__ Blo,
            const float* __restrict__ bias, float* __restrict__ C,
            int M, int N, int K) {
    extern __shared__ char smraw[];
    uint32_t sb = smem_u32(smraw);
    constexpr int OFF_AL = 10240, OFF_BH = 20480, OFF_BL = 30720, STG = 40960;
    int tid = threadIdx.x, lane = tid & 31, warp = tid >> 5;
    int wm = (warp & 3) * 32;
    int wn = (warp >> 2) * 64;
    int bm = blockIdx.y * 128, bn = blockIdx.x * 128;

    float acc[2][8][4];
#pragma unroll
    for (int a = 0; a < 2; ++a)
#pragma unroll
        for (int b = 0; b < 8; ++b)
#pragma unroll
            for (int c = 0; c < 4; ++c) acc[a][b][c] = 0.f;

    auto issue = [&](int kt, int s) {
        int k0 = kt * 32;
        uint32_t sbase = sb + s * STG;
#pragma unroll
        for (int i = 0; i < 2; ++i) {
            int idx = i * 256 + tid;
            int row = idx >> 2, c = idx & 3;
            uint32_t soff = sbase + row * 80 + c * 16;
            int ar = bm + row;
            int pa = (ar < M) ? 16 : 0;
            int arc = (ar < M) ? ar : 0;
            cp_cg(soff,          Ahi + (size_t)arc * K + k0 + c * 8, pa);
            cp_cg(soff + OFF_BH, Bhi + (size_t)(bn + row) * K + k0 + c * 8, 16);
            cp_cg(soff + OFF_AL, Alo + (size_t)arc * K + k0 + c * 8, pa);
            cp_cg(soff + OFF_BL, Blo + (size_t)(bn + row) * K + k0 + c * 8, 16);
        }
        asm volatile("cp.async.commit_group;" ::: "memory");
    };

    int KT = K / 32;
    issue(0, 0);
    for (int kt = 0; kt < KT; ++kt) {
        int s = kt & 1;
        if (kt + 1 < KT) {
            issue(kt + 1, s ^ 1);
            asm volatile("cp.async.wait_group 1;" ::: "memory");
        } else {
            asm volatile("cp.async.wait_group 0;" ::: "memory");
        }
        __syncthreads();
        uint32_t sbase = sb + s * STG;
#pragma unroll
        for (int kk = 0; kk < 2; ++kk) {
            uint32_t ah[2][4], al[2][4];
#pragma unroll
            for (int mt = 0; mt < 2; ++mt) {
                uint32_t addr = sbase + (uint32_t)(wm + mt * 16 + (lane & 15)) * 80
                              + kk * 32 + (lane >> 4) * 16;
                ldsm4(ah[mt], addr);
                ldsm4(al[mt], addr + OFF_AL);
            }
#pragma unroll
            for (int np = 0; np < 4; ++np) {
                int row = wn + np * 16 + (lane & 7) + ((lane >> 4) << 3);
                uint32_t addr = sbase + OFF_BH + (uint32_t)row * 80
                              + kk * 32 + ((lane >> 3) & 1) * 16;
                uint32_t tb[4];
                ldsm4(tb, addr);
#pragma unroll
                for (int mt = 0; mt < 2; ++mt) {
                    mma16816(acc[mt][2 * np],     ah[mt], tb);
                    mma16816(acc[mt][2 * np + 1], ah[mt], tb + 2);
                }
                uint32_t tl[4];
                ldsm4(tl, addr + (OFF_BL - OFF_BH));
#pragma unroll
                for (int mt = 0; mt < 2; ++mt) {
                    mma16816(acc[mt][2 * np],     ah[mt], tl);
                    mma16816(acc[mt][2 * np + 1], ah[mt], tl + 2);
                    mma16816(acc[mt][2 * np],     al[mt], tb);
                    mma16816(acc[mt][2 * np + 1], al[mt], tb + 2);
                }
            }
        }
        __syncthreads();
    }

#pragma unroll
    for (int mt = 0; mt < 2; ++mt) {
        int r0 = bm + wm + mt * 16 + (lane >> 2);
#pragma unroll
        for (int nt = 0; nt < 8; ++nt) {
            int c0 = bn + wn + nt * 8 + (lane & 3) * 2;
            float bx = bias ? __ldg(bias + c0) : 0.f;
            float by = bias ? __ldg(bias + c0 + 1) : 0.f;
            if (r0 < M) {
                float2 v = make_float2(acc[mt][nt][0] + bx, acc[mt][nt][1] + by);
                *(float2*)(C + (size_t)r0 * N + c0) = v;
            }
            if (r0 + 8 < M) {
                float2 v = make_float2(acc[mt][nt][2] + bx, acc[mt][nt][3] + by);
                *(float2*)(C + (size_t)(r0 + 8) * N + c0) = v;
            }
        }
    }
}

// k_mma_logit: single-pass bf16 GEMM vs interleaved [Wa;Wb], fused gated-logit
// epilogue. 2 CTAs/SM enforced (mainloop is register-leaner than k_mma_gemm3).
__global__ void __launch_bounds__(256, 2)
k_mma_logit(const __nv_bfloat16* __restrict__ Ahi, const __nv_bfloat16* __restrict__ Bhi,
            const float* __restrict__ ba, const float* __restrict__ bb,
            const float* __restrict__ Wc, float* __restrict__ logit,
            int M, int K) {
    extern __shared__ char smraw[];
    uint32_t sb = smem_u32(smraw);
    constexpr int OFF_BH = 10240, STG = 20480;
    int tid = threadIdx.x, lane = tid & 31, warp = tid >> 5;
    int wm = (warp & 3) * 32;
    int wn = (warp >> 2) * 64;
    int bm = blockIdx.y * 128, bn = blockIdx.x * 128;

    float acc[2][8][4];
#pragma unroll
    for (int a = 0; a < 2; ++a)
#pragma unroll
        for (int b = 0; b < 8; ++b)
#pragma unroll
            for (int c = 0; c < 4; ++c) acc[a][b][c] = 0.f;

    auto issue = [&](int kt, int s) {
        int k0 = kt * 32;
        uint32_t sbase = sb + s * STG;
#pragma unroll
        for (int i = 0; i < 2; ++i) {
            int idx = i * 256 + tid;
            int row = idx >> 2, c = idx & 3;
            uint32_t soff = sbase + row * 80 + c * 16;
            int ar = bm + row;
            int pa = (ar < M) ? 16 : 0;
            int arc = (ar < M) ? ar : 0;
            cp_cg(soff,          Ahi + (size_t)arc * K + k0 + c * 8, pa);
            cp_cg(soff + OFF_BH, Bhi + (size_t)(bn + row) * K + k0 + c * 8, 16);
        }
        asm volatile("cp.async.commit_group;" ::: "memory");
    };

    int KT = K / 32;
    issue(0, 0);
    for (int kt = 0; kt < KT; ++kt) {
        int s = kt & 1;
        if (kt + 1 < KT) {
            issue(kt + 1, s ^ 1);
            asm volatile("cp.async.wait_group 1;" ::: "memory");
        } else {
            asm volatile("cp.async.wait_group 0;" ::: "memory");
        }
        __syncthreads();
        uint32_t sbase = sb + s * STG;
#pragma unroll
        for (int kk = 0; kk < 2; ++kk) {
            uint32_t ah[2][4];
#pragma unroll
            for (int mt = 0; mt < 2; ++mt) {
                uint32_t addr = sbase + (uint32_t)(wm + mt * 16 + (lane & 15)) * 80
                              + kk * 32 + (lane >> 4) * 16;
                ldsm4(ah[mt], addr);
            }
#pragma unroll
            for (int np = 0; np < 4; ++np) {
                int row = wn + np * 16 + (lane & 7) + ((lane >> 4) << 3);
                uint32_t addr = sbase + OFF_BH + (uint32_t)row * 80
                              + kk * 32 + ((lane >> 3) & 1) * 16;
                uint32_t tb[4];
                ldsm4(tb, addr);
#pragma unroll
                for (int mt = 0; mt < 2; ++mt) {
                    mma16816(acc[mt][2 * np],     ah[mt], tb);
                    mma16816(acc[mt][2 * np + 1], ah[mt], tb + 2);
                }
            }
        }
        __syncthreads();
    }

    // fused gated-logit epilogue (interleaved B: col 2j = A_j, col 2j+1 = B_j)
#pragma unroll
    for (int mt = 0; mt < 2; ++mt) {
        float p0 = 0.f, p1 = 0.f;
#pragma unroll
        for (int nt = 0; nt < 8; ++nt) {
            int c0 = bn + wn + nt * 8 + (lane & 3) * 2;
            int j = c0 >> 1;
            float baj = __ldg(ba + j), bbj = __ldg(bb + j), wcj = __ldg(Wc + j);
            float s0 = 1.f / (1.f + expf(-(acc[mt][nt][1] + bbj)));
            p0 += tanhf(acc[mt][nt][0] + baj) * s0 * wcj;
            float s1 = 1.f / (1.f + expf(-(acc[mt][nt][3] + bbj)));
            p1 += tanhf(acc[mt][nt][2] + baj) * s1 * wcj;
        }
        int r0 = bm + wm + mt * 16 + (lane >> 2);
        if (r0 < M) atomicAdd(logit + r0, p0);
        if (r0 + 8 < M) atomicAdd(logit + r0 + 8, p1);
    }
}

// ---------------- CSR construction ----------------
__global__ void k_zero_csr(int* __restrict__ degE, int* __restrict__ degV) {
    int i = blockIdx.x * blockDim.x + threadIdx.x;
    if (i < ME) degE[i] = 0;
    if (i < NV) degV[i] = 0;
}

__global__ void k_count(const int* __restrict__ vi, const int* __restrict__ ei,
                        int* __restrict__ degV, int* __restrict__ degE) {
    int i = blockIdx.x * blockDim.x + threadIdx.x;
    if (i < EI) {
        atomicAdd(&degV[vi[i]], 1);
        atomicAdd(&degE[ei[i]], 1);
    }
}

__global__ void __launch_bounds__(1024)
k_scan(const int* __restrict__ cnt, int* __restrict__ off,
       int* __restrict__ cur, int n) {
    __shared__ int wsum[32];
    int tid = threadIdx.x, lane = tid & 31, w = tid >> 5;
    int chunk = (n + 1023) / 1024;
    int beg = min(tid * chunk, n);
    int end = min(beg + chunk, n);
    int s = 0;
    for (int i = beg; i < end; ++i) s += cnt[i];
    int v = s;
#pragma unroll
    for (int o = 1; o < 32; o <<= 1) {
        int u = __shfl_up_sync(0xffffffffu, v, o);
        if (lane >= o) v += u;
    }
    if (lane == 31) wsum[w] = v;
    __syncthreads();
    if (w == 0) {
        int ws = wsum[lane];
#pragma unroll
        for (int o = 1; o < 32; o <<= 1) {
            int u = __shfl_up_sync(0xffffffffu, ws, o);
            if (lane >= o) ws += u;
        }
        wsum[lane] = ws;
    }
    __syncthreads();
    int excl = v - s + (w > 0 ? wsum[w - 1] : 0);
    int run = excl;
    for (int i = beg; i < end; ++i) { off[i] = run; cur[i] = run; run += cnt[i]; }
    if (tid == 1023) off[n] = wsum[31];
}

__global__ void k_fill(const int* __restrict__ vi, const int* __restrict__ ei,
                       int* __restrict__ ecur, int* __restrict__ vcur,
                       int* __restrict__ elist, int* __restrict__ vlist) {
    int i = blockIdx.x * blockDim.x + threadIdx.x;
    if (i < EI) {
        int v = vi[i], e = ei[i];
        elist[atomicAdd(&ecur[e], 1)] = v;
        vlist[atomicAdd(&vcur[v], 1)] = e;
    }
}

// ---------------- v2e mean (+ edge logit / + bf16 hi emission) -------------
template <int D, bool WE>
__global__ void __launch_bounds__(D / 4)
k_v2e(const float* __restrict__ Hp, const float* __restrict__ we,
      float* __restrict__ Y, float* __restrict__ alpha,
      __nv_bfloat16* __restrict__ Yhi,
      const int* __restrict__ eoff, const int* __restrict__ elist) {
    constexpr int T = D / 4;
    int e = blockIdx.x;
    int beg = eoff[e], end = eoff[e + 1];
    int t = threadIdx.x;
    float4 acc = make_float4(0.f, 0.f, 0.f, 0.f);
    for (int i = beg; i < end; ++i) {
        const float4* row = (const float4*)(Hp + (size_t)elist[i] * D);
        float4 v = row[t];
        acc.x += v.x; acc.y += v.y; acc.z += v.z; acc.w += v.w;
    }
    float inv = 1.f / fmaxf((float)(end - beg), 1.f);
    float4 y = make_float4(acc.x * inv, acc.y * inv, acc.z * inv, acc.w * inv);
    ((float4*)(Y + (size_t)e * D))[t] = y;
    if (Yhi) {
        __nv_bfloat162* ph = (__nv_bfloat162*)(Yhi + (size_t)e * D);
        ph[2 * t]     = __nv_bfloat162(__float2bfloat16(y.x), __float2bfloat16(y.y));
        ph[2 * t + 1] = __nv_bfloat162(__float2bfloat16(y.z), __float2bfloat16(y.w));
    }
    if (WE) {
        float4 w4 = ((const float4*)we)[t];
        float dot = y.x * w4.x + y.y * w4.y + y.z * w4.z + y.w * w4.w;
        __shared__ float red[T];
        red[t] = dot;
        __syncthreads();
        for (int s = T / 2; s > 0; s >>= 1) {
            if (t < s) red[t] += red[t + s];
            __syncthreads();
        }
        if (t == 0) alpha[e] = red[0];
    }
}

// ---------------- per-vertex softmax stats ----------------
__global__ void k_vstats(const float* __restrict__ alpha,
                         const int* __restrict__ voff, const int* __restrict__ vlist,
                         float* __restrict__ vm, float* __restrict__ vwinv) {
    int v = blockIdx.x * blockDim.x + threadIdx.x;
    if (v >= NV) return;
    int beg = voff[v], end = voff[v + 1];
    float m = -INFINITY;
    for (int t = beg; t < end; ++t) {
        float a = alpha[vlist[t]];
        a = a > 0.f ? a : 0.2f * a;
        m = fmaxf(m, a);
    }
    float s = 0.f;
    for (int t = beg; t < end; ++t) {
        float a = alpha[vlist[t]];
        a = a > 0.f ? a : 0.2f * a;
        s += expf(a - m);
    }
    vm[v] = m;
    vwinv[v] = 1.f / (s + 1e-12f);
}

// ---------------- e2v: softmax-weighted sum (+ bf16 hi/lo emission) --------
template <int D, bool ELU>
__global__ void __launch_bounds__(D / 4)
k_e2v(const float* __restrict__ Y, float* __restrict__ Xo,
      __nv_bfloat16* __restrict__ Xhi, __nv_bfloat16* __restrict__ Xlo,
      const int* __restrict__ voff, const int* __restrict__ vlist,
      const float* __restrict__ alpha,
      const float* __restrict__ vm, const float* __restrict__ vwinv) {
    int v = blockIdx.x;
    int beg = voff[v], end = voff[v + 1];
    int t = threadIdx.x;
    float4 acc = make_float4(0.f, 0.f, 0.f, 0.f);
    float m = vm[v], winv = vwinv[v];
    for (int i = beg; i < end; ++i) {
        int e = vlist[i];
        float a = alpha[e];
        a = a > 0.f ? a : 0.2f * a;
        float w = expf(a - m) * winv;
        float4 yv = ((const float4*)(Y + (size_t)e * D))[t];
        acc.x += w * yv.x; acc.y += w * yv.y; acc.z += w * yv.z; acc.w += w * yv.w;
    }
    if (ELU) {
        acc.x = acc.x > 0.f ? acc.x : expm1f(acc.x);
        acc.y = acc.y > 0.f ? acc.y : expm1f(acc.y);
        acc.z = acc.z > 0.f ? acc.z : expm1f(acc.z);
        acc.w = acc.w > 0.f ? acc.w : expm1f(acc.w);
    }
    if (Xo) ((float4*)(Xo + (size_t)v * D))[t] = acc;
    if (Xhi) {
        float x[4] = {acc.x, acc.y, acc.z, acc.w};
        __nv_bfloat16 h[4];
#pragma unroll
        for (int j = 0; j < 4; ++j) h[j] = __float2bfloat16(x[j]);
        __nv_bfloat162* ph = (__nv_bfloat162*)(Xhi + (size_t)v * D);
        ph[2 * t]     = __nv_bfloat162(h[0], h[1]);
        ph[2 * t + 1] = __nv_bfloat162(h[2], h[3]);
        if (Xlo) {
            __nv_bfloat16 l[4];
#pragma unroll
            for (int j = 0; j < 4; ++j)
                l[j] = __float2bfloat16(x[j] - __bfloat162float(h[j]));
            __nv_bfloat162* pl = (__nv_bfloat162*)(Xlo + (size_t)v * D);
            pl[2 * t]     = __nv_bfloat162(l[0], l[1]);
            pl[2 * t + 1] = __nv_bfloat162(l[2], l[3]);
        }
    }
}

// ---------------- attention softmax pieces ----------------
__global__ void k_attn_init(float* __restrict__ gvec, unsigned* __restrict__ menc,
                            float* __restrict__ S, float* __restrict__ logit,
                            int n, const float* __restrict__ bc) {
    int i = blockIdx.x * blockDim.x + threadIdx.x;
    if (i < CDIM) gvec[i] = 0.f;
    if (i < n) logit[i] = bc[0];
    if (i == 0) { *menc = 0u; *S = 0.f; }
}

__global__ void __launch_bounds__(256)
k_maxred(const float* __restrict__ l, int n, unsigned* __restrict__ menc) {
    float m = -INFINITY;
    for (int i = blockIdx.x * blockDim.x + threadIdx.x; i < n; i += gridDim.x * blockDim.x)
        m = fmaxf(m, l[i]);
    __shared__ float red[256];
    red[threadIdx.x] = m;
    __syncthreads();
    for (int s = 128; s > 0; s >>= 1) {
        if (threadIdx.x < s) red[threadIdx.x] = fmaxf(red[threadIdx.x], red[threadIdx.x + s]);
        __syncthreads();
    }
    if (threadIdx.x == 0) atomicMax(menc, fenc(red[0]));
}

__global__ void __launch_bounds__(256)
k_sumexp(const float* __restrict__ l, int n, const unsigned* __restrict__ menc,
         float* __restrict__ S) {
    float m = fdec(*menc);
    float s = 0.f;
    for (int i = blockIdx.x * blockDim.x + threadIdx.x; i < n; i += gridDim.x * blockDim.x)
        s += expf(l[i] - m);
    __shared__ float red[256];
    red[threadIdx.x] = s;
    __syncthreads();
    for (int st = 128; st > 0; st >>= 1) {
        if (threadIdx.x < st) red[threadIdx.x] += red[threadIdx.x + st];
        __syncthreads();
    }
    if (threadIdx.x == 0) atomicAdd(S, red[0]);
}

__global__ void __launch_bounds__(256)
k_wsum(const float* __restrict__ x, const float* __restrict__ l, int n,
       const unsigned* __restrict__ menc, const float* __restrict__ S,
       float* __restrict__ gvec) {
    int c = blockIdx.x * 256 + threadIdx.x;
    float m = fdec(*menc);
    float invS = 1.f / *S;
    float acc = 0.f;
    for (int r = blockIdx.y; r < n; r += gridDim.y)
        acc += expf(l[r] - m) * invS * x[(size_t)r * CDIM + c];
    atomicAdd(&gvec[c], acc);
}

__global__ void k_gemv(const float* __restrict__ v, const float* __restrict__ W,
                       const float* __restrict__ b, float* __restrict__ out,
                       int R, int K) {
    int row = blockIdx.x * (blockDim.x >> 5) + (threadIdx.x >> 5);
    if (row >= R) return;
    int lane = threadIdx.x & 31;
    const float* wr = W + (size_t)row * K;
    float s = 0.f;
    for (int k = lane; k < K; k += 32) s += v[k] * wr[k];
    for (int o = 16; o; o >>= 1) s += __shfl_down_sync(0xffffffffu, s, o);
    if (lane == 0) out[row] = s + b[row];
}

__global__ void __launch_bounds__(256)
k_ln(const float* __restrict__ x, const float* __restrict__ g,
     const float* __restrict__ b, float* __restrict__ out, int D) {
    __shared__ float red[256];
    __shared__ float mu_s, rstd_s;
    float s = 0.f;
    for (int i = threadIdx.x; i < D; i += 256) s += x[i];
    red[threadIdx.x] = s;
    __syncthreads();
    for (int st = 128; st > 0; st >>= 1) {
        if (threadIdx.x < st) red[threadIdx.x] += red[threadIdx.x + st];
        __syncthreads();
    }
    if (threadIdx.x == 0) mu_s = red[0] / (float)D;
    __syncthreads();
    float mu = mu_s;
    float vs = 0.f;
    for (int i = threadIdx.x; i < D; i += 256) {
        float d = x[i] - mu;
        vs += d * d;
    }
    red[threadIdx.x] = vs;
    __syncthreads();
    for (int st = 128; st > 0; st >>= 1) {
        if (threadIdx.x < st) red[threadIdx.x] += red[threadIdx.x + st];
        __syncthreads();
    }
    if (threadIdx.x == 0) rstd_s = rsqrtf(red[0] / (float)D + 1e-5f);
    __syncthreads();
    float rstd = rstd_s;
    for (int i = threadIdx.x; i < D; i += 256)
        out[i] = (x[i] - mu) * rstd * g[i] + b[i];
}

// ---------------- host orchestration ----------------
extern "C" void kernel_launch(void* const* d_in, const int* in_sizes, int n_in,
                              void* d_out, int out_size) {
    // proven-clean footprint: 3 streams + 4 events
    static cudaStream_t st[NB];
    static cudaEvent_t evR, evD[NB];
    static bool inited = false;
    if (!inited) {
        for (int i = 0; i < NB; ++i)
            cudaStreamCreateWithFlags(&st[i], cudaStreamNonBlocking);
        cudaEventCreateWithFlags(&evR, cudaEventDisableTiming);
        for (int i = 0; i < NB; ++i)
            cudaEventCreateWithFlags(&evD[i], cudaEventDisableTiming);
        inited = true;
    }

    float *bufA0, *bufC0, *bufD0, *Y0, *ybuf0, *alpha0, *vm0, *vwinv0, *logits0;
    float *gvec0, *gout0, *gcat, *gcatn, *S0;
    unsigned* menc0;
    int *degE0, *eoff0, *ecur0, *degV0, *voff0, *vcur0, *elist0, *vlist0;
    __nv_bfloat16 *Acthi0, *Actlo0, *Wt0hi, *Wt0lo, *Wt1hi, *Wt1lo, *Wabhi;
    cudaGetSymbolAddress((void**)&bufA0, g_bufA);
    cudaGetSymbolAddress((void**)&bufC0, g_bufC);
    cudaGetSymbolAddress((void**)&bufD0, g_bufD);
    cudaGetSymbolAddress((void**)&Y0, g_Y);
    cudaGetSymbolAddress((void**)&ybuf0, g_ybuf);
    cudaGetSymbolAddress((void**)&alpha0, g_alpha);
    cudaGetSymbolAddress((void**)&vm0, g_vm);
    cudaGetSymbolAddress((void**)&vwinv0, g_vwinv);
    cudaGetSymbolAddress((void**)&logits0, g_logits);
    cudaGetSymbolAddress((void**)&gvec0, g_gvec);
    cudaGetSymbolAddress((void**)&gout0, g_gout);
    cudaGetSymbolAddress((void**)&gcat, g_gcat);
    cudaGetSymbolAddress((void**)&gcatn, g_gcatn);
    cudaGetSymbolAddress((void**)&menc0, g_menc);
    cudaGetSymbolAddress((void**)&S0, g_S);
    cudaGetSymbolAddress((void**)&degE0, g_degE);
    cudaGetSymbolAddress((void**)&eoff0, g_eoff);
    cudaGetSymbolAddress((void**)&ecur0, g_ecur);
    cudaGetSymbolAddress((void**)&degV0, g_degV);
    cudaGetSymbolAddress((void**)&voff0, g_voff);
    cudaGetSymbolAddress((void**)&vcur0, g_vcur);
    cudaGetSymbolAddress((void**)&elist0, g_elist);
    cudaGetSymbolAddress((void**)&vlist0, g_vlist);
    cudaGetSymbolAddress((void**)&Acthi0, g_Acthi);
    cudaGetSymbolAddress((void**)&Actlo0, g_Actlo);
    cudaGetSymbolAddress((void**)&Wt0hi, g_Wt0hi);
    cudaGetSymbolAddress((void**)&Wt0lo, g_Wt0lo);
    cudaGetSymbolAddress((void**)&Wt1hi, g_Wt1hi);
    cudaGetSymbolAddress((void**)&Wt1lo, g_Wt1lo);
    cudaGetSymbolAddress((void**)&Wabhi, g_Wabhi);

    const int GSMEM3 = 81920, GSMEM1 = 40960;
    cudaFuncSetAttribute(k_mma_gemm3, cudaFuncAttributeMaxDynamicSharedMemorySize, GSMEM3);
    cudaFuncSetAttribute(k_mma_logit, cudaFuncAttributeMaxDynamicSharedMemorySize, GSMEM1);

    int xi[3], vii[3], eii[3];
    if (in_sizes[1] == NV * CDIM) {
        for (int b = 0; b < 3; ++b) { xi[b] = b; vii[b] = 3 + 2 * b; eii[b] = 4 + 2 * b; }
    } else {
        for (int b = 0; b < 3; ++b) { xi[b] = 3 * b; vii[b] = 3 * b + 1; eii[b] = 3 * b + 2; }
    }
    const float* Wt0  = (const float*)d_in[9];
    const float* bt0  = (const float*)d_in[10];
    const float* we0  = (const float*)d_in[11];
    const float* Wt1  = (const float*)d_in[12];
    const float* bt1  = (const float*)d_in[13];
    const float* we1  = (const float*)d_in[14];
    const float* Wa   = (const float*)d_in[15];
    const float* ba   = (const float*)d_in[16];
    const float* Wb   = (const float*)d_in[17];
    const float* bb   = (const float*)d_in[18];
    const float* Wc   = (const float*)d_in[19];
    const float* bc   = (const float*)d_in[20];
    const float* Wout = (const float*)d_in[21];
    const float* bout = (const float*)d_in[22];
    const float* gbn  = (const float*)d_in[23];
    const float* bbn  = (const float*)d_in[24];
    const float* gbn2 = (const float*)d_in[25];
    const float* bbn2 = (const float*)d_in[26];
    const float* Wf   = (const float*)d_in[27];
    const float* bf   = (const float*)d_in[28];

    const int EB = (EI + 255) / 256;

    // shared weight prep on the capture stream
    k_split<<<512, 256>>>(Wt0, Wt0hi, Wt0lo, 512 * 1024 / 4);
    k_split<<<512, 256>>>(Wt1, Wt1hi, Wt1lo, 1024 * 512 / 4);
    k_split_inter<<<512, 256>>>(Wa, Wb, Wabhi);

    cudaEventRecord(evR, 0);
    for (int b = 0; b < NB; ++b) cudaStreamWaitEvent(st[b], evR, 0);

    for (int b = 0; b < NB; ++b) {
        cudaStream_t s = st[b];
        const float* X = (const float*)d_in[xi[b]];
        const int* vi = (const int*)d_in[vii[b]];
        const int* ei = (const int*)d_in[eii[b]];

        float* bufA = bufA0 + (size_t)b * NV * HIDD;
        float* bufC = bufC0 + (size_t)b * NV * CDIM;
        float* bufD = bufD0 + (size_t)b * NV * CDIM;
        float* Y    = Y0    + (size_t)b * ME * CDIM;
        float* ybuf = ybuf0 + (size_t)b * ME * CDIM;
        float* alpha = alpha0 + (size_t)b * ME;
        float* vm = vm0 + (size_t)b * NV;
        float* vwinv = vwinv0 + (size_t)b * NV;
        float* logits = logits0 + (size_t)b * NV;
        float* gvec = gvec0 + (size_t)b * CDIM;
        float* gout = gout0 + (size_t)b * CDIM;
        unsigned* menc = menc0 + b;
        float* S = S0 + b;
        int* degE = degE0 + (size_t)b * ME;
        int* eoff = eoff0 + (size_t)b * (ME + 1);
        int* ecur = ecur0 + (size_t)b * ME;
        int* degV = degV0 + (size_t)b * NV;
        int* voff = voff0 + (size_t)b * (NV + 1);
        int* vcur = vcur0 + (size_t)b * NV;
        int* elist = elist0 + (size_t)b * EI;
        int* vlist = vlist0 + (size_t)b * EI;
        __nv_bfloat16* Acthi = Acthi0 + (size_t)b * NV * CDIM;
        __nv_bfloat16* Actlo = Actlo0 + (size_t)b * NV * CDIM;

        // activation split + layer-1 GEMM
        k_split<<<(NV * CDIM / 4 + 255) / 256, 256, 0, s>>>(X, Acthi, Actlo, NV * CDIM / 4);
        {
            dim3 g(HIDD / 128, (NV + 127) / 128);
            k_mma_gemm3<<<g, 256, GSMEM3, s>>>(Acthi, Actlo, Wt0hi, Wt0lo, bt0, bufA, NV, HIDD, CDIM);
        }

        // CSR
        k_zero_csr<<<(NV + 255) / 256, 256, 0, s>>>(degE, degV);
        k_count<<<EB, 256, 0, s>>>(vi, ei, degV, degE);
        k_scan<<<1, 1024, 0, s>>>(degE, eoff, ecur, ME);
        k_scan<<<1, 1024, 0, s>>>(degV, voff, vcur, NV);
        k_fill<<<EB, 256, 0, s>>>(vi, ei, ecur, vcur, elist, vlist);

        // layer 1 aggregation (elu) -> bf16 hi/lo for layer-2 GEMM
        k_v2e<HIDD, true><<<ME, HIDD / 4, 0, s>>>(bufA, we0, Y, alpha, nullptr, eoff, elist);
        k_vstats<<<(NV + 255) / 256, 256, 0, s>>>(alpha, voff, vlist, vm, vwinv);
        k_e2v<HIDD, true><<<NV, HIDD / 4, 0, s>>>(Y, nullptr, Acthi, Actlo,
                                                  voff, vlist, alpha, vm, vwinv);

        // layer 2
        {
            dim3 g(CDIM / 128, (NV + 127) / 128);
            k_mma_gemm3<<<g, 256, GSMEM3, s>>>(Acthi, Actlo, Wt1hi, Wt1lo, bt1, bufC, NV, CDIM, HIDD);
        }
        k_v2e<CDIM, true><<<ME, CDIM / 4, 0, s>>>(bufC, we1, Y, alpha, nullptr, eoff, elist);
        k_vstats<<<(NV + 255) / 256, 256, 0, s>>>(alpha, voff, vlist, vm, vwinv);
        k_e2v<CDIM, false><<<NV, CDIM / 4, 0, s>>>(Y, bufD, Acthi, nullptr,
                                                   voff, vlist, alpha, vm, vwinv);

        // y = v2e_mean(h): fp32 + bf16 hi (into Actlo)
        k_v2e<CDIM, false><<<ME, CDIM / 4, 0, s>>>(bufD, nullptr, ybuf, alpha, Actlo, eoff, elist);

        // gated attention on h — fused-logit GEMM (2 CTAs/SM)
        k_attn_init<<<(NV + 255) / 256, 256, 0, s>>>(gvec, menc, S, logits, NV, bc);
        {
            dim3 g(512 / 128, (NV + 127) / 128);
            k_mma_logit<<<g, 256, GSMEM1, s>>>(Acthi, Wabhi, ba, bb, Wc, logits, NV, CDIM);
        }
        k_maxred<<<40, 256, 0, s>>>(logits, NV, menc);
        k_sumexp<<<40, 256, 0, s>>>(logits, NV, menc, S);
        {
            dim3 g(CDIM / 256, 125);
            k_wsum<<<g, 256, 0, s>>>(bufD, logits, NV, menc, S, gvec);
        }
        k_gemv<<<128, 256, 0, s>>>(gvec, Wout, bout, gout, CDIM, CDIM);
        k_ln<<<1, 256, 0, s>>>(gout, gbn, bbn, gcat + (size_t)b * CDIM, CDIM);

        // gated attention on y — fused-logit GEMM
        k_attn_init<<<(NV + 255) / 256, 256, 0, s>>>(gvec, menc, S, logits, ME, bc);
        {
            dim3 g(512 / 128, (ME + 127) / 128);
            k_mma_logit<<<g, 256, GSMEM1, s>>>(Actlo, Wabhi, ba, bb, Wc, logits, ME, CDIM);
        }
        k_maxred<<<20, 256, 0, s>>>(logits, ME, menc);
        k_sumexp<<<20, 256, 0, s>>>(logits, ME, menc, S);
        {
            dim3 g(CDIM / 256, 125);
            k_wsum<<<g, 256, 0, s>>>(ybuf, logits, ME, menc, S, gvec);
        }
        k_gemv<<<128, 256, 0, s>>>(gvec, Wout, bout, gout, CDIM, CDIM);
        k_ln<<<1, 256, 0, s>>>(gout, gbn, bbn, gcat + (size_t)(3 + b) * CDIM, CDIM);

        cudaEventRecord(evD[b], s);
    }

    for (int b = 0; b < NB; ++b) cudaStreamWaitEvent(0, evD[b], 0);

    k_ln<<<1, 256>>>(gcat, gbn2, bbn2, gcatn, 6 * CDIM);
    k_gemv<<<2, 256>>>(gcatn, Wf, bf, (float*)d_out, 10, 6 * CDIM);
}

// round 15
// speedup vs baseline: 1.5155x; 1.5155x over previous
#include <cuda_runtime.h>
#include <cuda_bf16.h>
#include <math.h>
#include <stdint.h>

// Problem constants
#define NV   20000
#define ME   5000
#define EI   160000
#define CDIM 1024
#define HIDD 512
#define NB   3

// ---------------- device scratch (static, no allocation) ----------------
__device__ __align__(16) float g_bufA[NB][(size_t)NV * HIDD];   // Y1 [ME,512] (region)
__device__ __align__(16) float g_bufC[NB][(size_t)NV * CDIM];   // h1 [NV,512] (region)
__device__ __align__(16) float g_bufD[NB][(size_t)NV * CDIM];   // h  [NV,1024]
__device__ __align__(16) float g_Y[NB][(size_t)ME * CDIM];      // Y2 [ME,1024]
__device__ __align__(16) float g_ybuf[NB][(size_t)ME * CDIM];   // y  [ME,1024]
__device__ float g_alpha[NB][ME];
__device__ float g_vm[NB][NV];
__device__ float g_vwinv[NB][NV];
__device__ float g_logits[NB][NV];

__device__ int g_degE[NB][ME], g_eoff[NB][ME + 1], g_ecur[NB][ME];
__device__ int g_degV[NB][NV], g_voff[NB][NV + 1], g_vcur[NB][NV];
__device__ int g_elist[NB][EI];
__device__ int g_vlist[NB][EI];

__device__ float g_gvec[NB][CDIM];
__device__ float g_gout[NB][CDIM];
__device__ unsigned g_menc[NB];
__device__ float g_S[NB];

__device__ __align__(16) __nv_bfloat16 g_Acthi[NB][(size_t)NV * CDIM];
__device__ __align__(16) __nv_bfloat16 g_Actlo[NB][(size_t)NV * CDIM];

// shared weights
__device__ float g_gcat[6 * CDIM];
__device__ float g_gcatn[6 * CDIM];
__device__ __align__(16) __nv_bfloat16 g_Wt0hi[512 * 1024], g_Wt0lo[512 * 1024];
__device__ __align__(16) __nv_bfloat16 g_Wt1hi[1024 * 512], g_Wt1lo[1024 * 512];
__device__ __align__(16) __nv_bfloat16 g_Wabhi[512 * 1024];   // interleaved Wa/Wb rows

// ---------------- helpers ----------------
__device__ __forceinline__ uint32_t smem_u32(const void* p) {
    uint32_t a;
    asm("{ .reg .u64 t; cvta.to.shared.u64 t, %1; cvt.u32.u64 %0, t; }"
        : "=r"(a) : "l"(p));
    return a;
}

__device__ __forceinline__ void cp_cg(uint32_t s, const void* g, int bytes) {
    asm volatile("cp.async.cg.shared.global [%0], [%1], 16, %2;"
                 :: "r"(s), "l"(g), "r"(bytes) : "memory");
}

__device__ __forceinline__ void ldsm4(uint32_t* r, uint32_t addr) {
    asm volatile("ldmatrix.sync.aligned.m8n8.x4.shared.b16 {%0,%1,%2,%3}, [%4];"
                 : "=r"(r[0]), "=r"(r[1]), "=r"(r[2]), "=r"(r[3]) : "r"(addr));
}

__device__ __forceinline__ void mma16816(float* d, const uint32_t* a, const uint32_t* b) {
    asm volatile(
        "mma.sync.aligned.m16n8k16.row.col.f32.bf16.bf16.f32 "
        "{%0,%1,%2,%3}, {%4,%5,%6,%7}, {%8,%9}, {%0,%1,%2,%3};"
        : "+f"(d[0]), "+f"(d[1]), "+f"(d[2]), "+f"(d[3])
        : "r"(a[0]), "r"(a[1]), "r"(a[2]), "r"(a[3]), "r"(b[0]), "r"(b[1]));
}

__device__ __forceinline__ unsigned fenc(float f) {
    unsigned u = __float_as_uint(f);
    return (u & 0x80000000u) ? ~u : (u | 0x80000000u);
}
__device__ __forceinline__ float fdec(unsigned e) {
    unsigned u = (e & 0x80000000u) ? (e & 0x7FFFFFFFu) : ~e;
    return __uint_as_float(u);
}

// ---------------- fp32 -> bf16 hi/lo split (weights) ----------------
__global__ void __launch_bounds__(256)
k_split(const float* __restrict__ src, __nv_bfloat16* __restrict__ hi,
        __nv_bfloat16* __restrict__ lo, int n4) {
    int i = blockIdx.x * blockDim.x + threadIdx.x;
    if (i >= n4) return;
    float4 v = ((const float4*)src)[i];
    __nv_bfloat16 h[4], l[4];
    float x[4] = {v.x, v.y, v.z, v.w};
#pragma unroll
    for (int j = 0; j < 4; ++j) {
        h[j] = __float2bfloat16(x[j]);
        l[j] = __float2bfloat16(x[j] - __bfloat162float(h[j]));
    }
    ((__nv_bfloat162*)hi)[2 * i]     = __nv_bfloat162(h[0], h[1]);
    ((__nv_bfloat162*)hi)[2 * i + 1] = __nv_bfloat162(h[2], h[3]);
    ((__nv_bfloat162*)lo)[2 * i]     = __nv_bfloat162(l[0], l[1]);
    ((__nv_bfloat162*)lo)[2 * i + 1] = __nv_bfloat162(l[2], l[3]);
}

// interleave Wa/Wb rows: out row 2j = Wa[j], row 2j+1 = Wb[j]; bf16 hi only
__global__ void __launch_bounds__(256)
k_split_inter(const float* __restrict__ Wa, const float* __restrict__ Wb,
              __nv_bfloat16* __restrict__ hi) {
    int i = blockIdx.x * 256 + threadIdx.x;
    if (i >= 512 * 256) return;
    int row = i >> 8, c4 = i & 255;
    const float* src = ((row & 1) ? Wb : Wa) + (size_t)(row >> 1) * 1024 + c4 * 4;
    float4 v = *(const float4*)src;
    __nv_bfloat162* ph = (__nv_bfloat162*)(hi + (size_t)row * 1024 + c4 * 4);
    ph[0] = __nv_bfloat162(__float2bfloat16(v.x), __float2bfloat16(v.y));
    ph[1] = __nv_bfloat162(__float2bfloat16(v.z), __float2bfloat16(v.w));
}

// ---------------- bf16 tensor-core GEMM ----------------
// 3-pass Ootomo split, C = A@B^T + bias (bias masked by degE>0 when given).
__global__ void __launch_bounds__(256, 2)
k_mma_gemm3(const __nv_bfloat16* __restrict__ Ahi, const __nv_bfloat16* __restrict__ Alo,
            const __nv_bfloat16* __restrict__ Bhi, const __nv_bfloat16* __restrict__ Blo,
            const float* __restrict__ bias, const int* __restrict__ degE,
            float* __restrict__ C, int M, int N, int K) {
    extern __shared__ char smraw[];
    uint32_t sb = smem_u32(smraw);
    constexpr int OFF_AL = 10240, OFF_BH = 20480, OFF_BL = 30720, STG = 40960;
    int tid = threadIdx.x, lane = tid & 31, warp = tid >> 5;
    int wm = (warp & 3) * 32;
    int wn = (warp >> 2) * 64;
    int bm = blockIdx.y * 128, bn = blockIdx.x * 128;

    float acc[2][8][4];
#pragma unroll
    for (int a = 0; a < 2; ++a)
#pragma unroll
        for (int b = 0; b < 8; ++b)
#pragma unroll
            for (int c = 0; c < 4; ++c) acc[a][b][c] = 0.f;

    auto issue = [&](int kt, int s) {
        int k0 = kt * 32;
        uint32_t sbase = sb + s * STG;
#pragma unroll
        for (int i = 0; i < 2; ++i) {
            int idx = i * 256 + tid;
            int row = idx >> 2, c = idx & 3;
            uint32_t soff = sbase + row * 80 + c * 16;
            int ar = bm + row;
            int pa = (ar < M) ? 16 : 0;
            int arc = (ar < M) ? ar : 0;
            cp_cg(soff,          Ahi + (size_t)arc * K + k0 + c * 8, pa);
            cp_cg(soff + OFF_BH, Bhi + (size_t)(bn + row) * K + k0 + c * 8, 16);
            cp_cg(soff + OFF_AL, Alo + (size_t)arc * K + k0 + c * 8, pa);
            cp_cg(soff + OFF_BL, Blo + (size_t)(bn + row) * K + k0 + c * 8, 16);
        }
        asm volatile("cp.async.commit_group;" ::: "memory");
    };

    int KT = K / 32;
    issue(0, 0);
    for (int kt = 0; kt < KT; ++kt) {
        int s = kt & 1;
        if (kt + 1 < KT) {
            issue(kt + 1, s ^ 1);
            asm volatile("cp.async.wait_group 1;" ::: "memory");
        } else {
            asm volatile("cp.async.wait_group 0;" ::: "memory");
        }
        __syncthreads();
        uint32_t sbase = sb + s * STG;
#pragma unroll
        for (int kk = 0; kk < 2; ++kk) {
            uint32_t ah[2][4], al[2][4];
#pragma unroll
            for (int mt = 0; mt < 2; ++mt) {
                uint32_t addr = sbase + (uint32_t)(wm + mt * 16 + (lane & 15)) * 80
                              + kk * 32 + (lane >> 4) * 16;
                ldsm4(ah[mt], addr);
                ldsm4(al[mt], addr + OFF_AL);
            }
#pragma unroll
            for (int np = 0; np < 4; ++np) {
                int row = wn + np * 16 + (lane & 7) + ((lane >> 4) << 3);
                uint32_t addr = sbase + OFF_BH + (uint32_t)row * 80
                              + kk * 32 + ((lane >> 3) & 1) * 16;
                uint32_t tb[4];
                ldsm4(tb, addr);
#pragma unroll
                for (int mt = 0; mt < 2; ++mt) {
                    mma16816(acc[mt][2 * np],     ah[mt], tb);
                    mma16816(acc[mt][2 * np + 1], ah[mt], tb + 2);
                }
                uint32_t tl[4];
                ldsm4(tl, addr + (OFF_BL - OFF_BH));
#pragma unroll
                for (int mt = 0; mt < 2; ++mt) {
                    mma16816(acc[mt][2 * np],     ah[mt], tl);
                    mma16816(acc[mt][2 * np + 1], ah[mt], tl + 2);
                    mma16816(acc[mt][2 * np],     al[mt], tb);
                    mma16816(acc[mt][2 * np + 1], al[mt], tb + 2);
                }
            }
        }
        __syncthreads();
    }

#pragma unroll
    for (int mt = 0; mt < 2; ++mt) {
        int r0 = bm + wm + mt * 16 + (lane >> 2);
        float m0 = 1.f, m1 = 1.f;
        if (degE) {
            if (r0 < M) m0 = (degE[r0] > 0) ? 1.f : 0.f;
            if (r0 + 8 < M) m1 = (degE[r0 + 8] > 0) ? 1.f : 0.f;
        }
#pragma unroll
        for (int nt = 0; nt < 8; ++nt) {
            int c0 = bn + wn + nt * 8 + (lane & 3) * 2;
            float bx = bias ? __ldg(bias + c0) : 0.f;
            float by = bias ? __ldg(bias + c0 + 1) : 0.f;
            if (r0 < M) {
                float2 v = make_float2(acc[mt][nt][0] + bx * m0, acc[mt][nt][1] + by * m0);
                *(float2*)(C + (size_t)r0 * N + c0) = v;
            }
            if (r0 + 8 < M) {
                float2 v = make_float2(acc[mt][nt][2] + bx * m1, acc[mt][nt][3] + by * m1);
                *(float2*)(C + (size_t)(r0 + 8) * N + c0) = v;
            }
        }
    }
}

// k_mma_logit: single-pass bf16 GEMM vs interleaved [Wa;Wb], fused gated-logit
// epilogue. 2 CTAs/SM enforced.
__global__ void __launch_bounds__(256, 2)
k_mma_logit(const __nv_bfloat16* __restrict__ Ahi, const __nv_bfloat16* __restrict__ Bhi,
            const float* __restrict__ ba, const float* __restrict__ bb,
            const float* __restrict__ Wc, float* __restrict__ logit,
            int M, int K) {
    extern __shared__ char smraw[];
    uint32_t sb = smem_u32(smraw);
    constexpr int OFF_BH = 10240, STG = 20480;
    int tid = threadIdx.x, lane = tid & 31, warp = tid >> 5;
    int wm = (warp & 3) * 32;
    int wn = (warp >> 2) * 64;
    int bm = blockIdx.y * 128, bn = blockIdx.x * 128;

    float acc[2][8][4];
#pragma unroll
    for (int a = 0; a < 2; ++a)
#pragma unroll
        for (int b = 0; b < 8; ++b)
#pragma unroll
            for (int c = 0; c < 4; ++c) acc[a][b][c] = 0.f;

    auto issue = [&](int kt, int s) {
        int k0 = kt * 32;
        uint32_t sbase = sb + s * STG;
#pragma unroll
        for (int i = 0; i < 2; ++i) {
            int idx = i * 256 + tid;
            int row = idx >> 2, c = idx & 3;
            uint32_t soff = sbase + row * 80 + c * 16;
            int ar = bm + row;
            int pa = (ar < M) ? 16 : 0;
            int arc = (ar < M) ? ar : 0;
            cp_cg(soff,          Ahi + (size_t)arc * K + k0 + c * 8, pa);
            cp_cg(soff + OFF_BH, Bhi + (size_t)(bn + row) * K + k0 + c * 8, 16);
        }
        asm volatile("cp.async.commit_group;" ::: "memory");
    };

    int KT = K / 32;
    issue(0, 0);
    for (int kt = 0; kt < KT; ++kt) {
        int s = kt & 1;
        if (kt + 1 < KT) {
            issue(kt + 1, s ^ 1);
            asm volatile("cp.async.wait_group 1;" ::: "memory");
        } else {
            asm volatile("cp.async.wait_group 0;" ::: "memory");
        }
        __syncthreads();
        uint32_t sbase = sb + s * STG;
#pragma unroll
        for (int kk = 0; kk < 2; ++kk) {
            uint32_t ah[2][4];
#pragma unroll
            for (int mt = 0; mt < 2; ++mt) {
                uint32_t addr = sbase + (uint32_t)(wm + mt * 16 + (lane & 15)) * 80
                              + kk * 32 + (lane >> 4) * 16;
                ldsm4(ah[mt], addr);
            }
#pragma unroll
            for (int np = 0; np < 4; ++np) {
                int row = wn + np * 16 + (lane & 7) + ((lane >> 4) << 3);
                uint32_t addr = sbase + OFF_BH + (uint32_t)row * 80
                              + kk * 32 + ((lane >> 3) & 1) * 16;
                uint32_t tb[4];
                ldsm4(tb, addr);
#pragma unroll
                for (int mt = 0; mt < 2; ++mt) {
                    mma16816(acc[mt][2 * np],     ah[mt], tb);
                    mma16816(acc[mt][2 * np + 1], ah[mt], tb + 2);
                }
            }
        }
        __syncthreads();
    }

#pragma unroll
    for (int mt = 0; mt < 2; ++mt) {
        float p0 = 0.f, p1 = 0.f;
#pragma unroll
        for (int nt = 0; nt < 8; ++nt) {
            int c0 = bn + wn + nt * 8 + (lane & 3) * 2;
            int j = c0 >> 1;
            float baj = __ldg(ba + j), bbj = __ldg(bb + j), wcj = __ldg(Wc + j);
            float s0 = 1.f / (1.f + expf(-(acc[mt][nt][1] + bbj)));
            p0 += tanhf(acc[mt][nt][0] + baj) * s0 * wcj;
            float s1 = 1.f / (1.f + expf(-(acc[mt][nt][3] + bbj)));
            p1 += tanhf(acc[mt][nt][2] + baj) * s1 * wcj;
        }
        int r0 = bm + wm + mt * 16 + (lane >> 2);
        if (r0 < M) atomicAdd(logit + r0, p0);
        if (r0 + 8 < M) atomicAdd(logit + r0 + 8, p1);
    }
}

// ---------------- CSR construction ----------------
__global__ void k_zero_csr(int* __restrict__ degE, int* __restrict__ degV) {
    int i = blockIdx.x * blockDim.x + threadIdx.x;
    if (i < ME) degE[i] = 0;
    if (i < NV) degV[i] = 0;
}

__global__ void k_count(const int* __restrict__ vi, const int* __restrict__ ei,
                        int* __restrict__ degV, int* __restrict__ degE) {
    int i = blockIdx.x * blockDim.x + threadIdx.x;
    if (i < EI) {
        atomicAdd(&degV[vi[i]], 1);
        atomicAdd(&degE[ei[i]], 1);
    }
}

__global__ void __launch_bounds__(1024)
k_scan(const int* __restrict__ cnt, int* __restrict__ off,
       int* __restrict__ cur, int n) {
    __shared__ int wsum[32];
    int tid = threadIdx.x, lane = tid & 31, w = tid >> 5;
    int chunk = (n + 1023) / 1024;
    int beg = min(tid * chunk, n);
    int end = min(beg + chunk, n);
    int s = 0;
    for (int i = beg; i < end; ++i) s += cnt[i];
    int v = s;
#pragma unroll
    for (int o = 1; o < 32; o <<= 1) {
        int u = __shfl_up_sync(0xffffffffu, v, o);
        if (lane >= o) v += u;
    }
    if (lane == 31) wsum[w] = v;
    __syncthreads();
    if (w == 0) {
        int ws = wsum[lane];
#pragma unroll
        for (int o = 1; o < 32; o <<= 1) {
            int u = __shfl_up_sync(0xffffffffu, ws, o);
            if (lane >= o) ws += u;
        }
        wsum[lane] = ws;
    }
    __syncthreads();
    int excl = v - s + (w > 0 ? wsum[w - 1] : 0);
    int run = excl;
    for (int i = beg; i < end; ++i) { off[i] = run; cur[i] = run; run += cnt[i]; }
    if (tid == 1023) off[n] = wsum[31];
}

__global__ void k_fill(const int* __restrict__ vi, const int* __restrict__ ei,
                       int* __restrict__ ecur, int* __restrict__ vcur,
                       int* __restrict__ elist, int* __restrict__ vlist) {
    int i = blockIdx.x * blockDim.x + threadIdx.x;
    if (i < EI) {
        int v = vi[i], e = ei[i];
        elist[atomicAdd(&ecur[e], 1)] = v;
        vlist[atomicAdd(&vcur[v], 1)] = e;
    }
}

// ---------------- v2e mean (fp32 optional, bf16 hi/lo optional) ------------
template <int D>
__global__ void __launch_bounds__(D / 4)
k_v2e(const float* __restrict__ Hp, float* __restrict__ Y,
      __nv_bfloat16* __restrict__ Yhi, __nv_bfloat16* __restrict__ Ylo,
      const int* __restrict__ eoff, const int* __restrict__ elist) {
    int e = blockIdx.x;
    int beg = eoff[e], end = eoff[e + 1];
    int t = threadIdx.x;
    float4 acc = make_float4(0.f, 0.f, 0.f, 0.f);
    for (int i = beg; i < end; ++i) {
        const float4* row = (const float4*)(Hp + (size_t)elist[i] * D);
        float4 v = row[t];
        acc.x += v.x; acc.y += v.y; acc.z += v.z; acc.w += v.w;
    }
    float inv = 1.f / fmaxf((float)(end - beg), 1.f);
    float x[4] = {acc.x * inv, acc.y * inv, acc.z * inv, acc.w * inv};
    if (Y) {
        ((float4*)(Y + (size_t)e * D))[t] = make_float4(x[0], x[1], x[2], x[3]);
    }
    if (Yhi) {
        __nv_bfloat16 h[4];
#pragma unroll
        for (int j = 0; j < 4; ++j) h[j] = __float2bfloat16(x[j]);
        __nv_bfloat162* ph = (__nv_bfloat162*)(Yhi + (size_t)e * D);
        ph[2 * t]     = __nv_bfloat162(h[0], h[1]);
        ph[2 * t + 1] = __nv_bfloat162(h[2], h[3]);
        if (Ylo) {
            __nv_bfloat16 l[4];
#pragma unroll
            for (int j = 0; j < 4; ++j)
                l[j] = __float2bfloat16(x[j] - __bfloat162float(h[j]));
            __nv_bfloat162* pl = (__nv_bfloat162*)(Ylo + (size_t)e * D);
            pl[2 * t]     = __nv_bfloat162(l[0], l[1]);
            pl[2 * t + 1] = __nv_bfloat162(l[2], l[3]);
        }
    }
}

// ---------------- per-edge attention logit: alpha[e] = Y[e]·we -------------
template <int D>
__global__ void __launch_bounds__(D / 4)
k_alpha(const float* __restrict__ Y, const float* __restrict__ we,
        float* __restrict__ alpha) {
    constexpr int T = D / 4;
    int e = blockIdx.x, t = threadIdx.x;
    float4 y = ((const float4*)(Y + (size_t)e * D))[t];
    float4 w = ((const float4*)we)[t];
    float dot = y.x * w.x + y.y * w.y + y.z * w.z + y.w * w.w;
    __shared__ float red[T];
    red[t] = dot;
    __syncthreads();
    for (int s = T / 2; s > 0; s >>= 1) {
        if (t < s) red[t] += red[t + s];
        __syncthreads();
    }
    if (t == 0) alpha[e] = red[0];
}

// ---------------- per-vertex softmax stats ----------------
__global__ void k_vstats(const float* __restrict__ alpha,
                         const int* __restrict__ voff, const int* __restrict__ vlist,
                         float* __restrict__ vm, float* __restrict__ vwinv) {
    int v = blockIdx.x * blockDim.x + threadIdx.x;
    if (v >= NV) return;
    int beg = voff[v], end = voff[v + 1];
    float m = -INFINITY;
    for (int t = beg; t < end; ++t) {
        float a = alpha[vlist[t]];
        a = a > 0.f ? a : 0.2f * a;
        m = fmaxf(m, a);
    }
    float s = 0.f;
    for (int t = beg; t < end; ++t) {
        float a = alpha[vlist[t]];
        a = a > 0.f ? a : 0.2f * a;
        s += expf(a - m);
    }
    vm[v] = m;
    vwinv[v] = 1.f / (s + 1e-12f);
}

// ---------------- e2v: softmax-weighted sum (+ bf16 hi emission) -----------
template <int D, bool ELU>
__global__ void __launch_bounds__(D / 4)
k_e2v(const float* __restrict__ Y, float* __restrict__ Xo,
      __nv_bfloat16* __restrict__ Xhi,
      const int* __restrict__ voff, const int* __restrict__ vlist,
      const float* __restrict__ alpha,
      const float* __restrict__ vm, const float* __restrict__ vwinv) {
    int v = blockIdx.x;
    int beg = voff[v], end = voff[v + 1];
    int t = threadIdx.x;
    float4 acc = make_float4(0.f, 0.f, 0.f, 0.f);
    float m = vm[v], winv = vwinv[v];
    for (int i = beg; i < end; ++i) {
        int e = vlist[i];
        float a = alpha[e];
        a = a > 0.f ? a : 0.2f * a;
        float w = expf(a - m) * winv;
        float4 yv = ((const float4*)(Y + (size_t)e * D))[t];
        acc.x += w * yv.x; acc.y += w * yv.y; acc.z += w * yv.z; acc.w += w * yv.w;
    }
    if (ELU) {
        acc.x = acc.x > 0.f ? acc.x : expm1f(acc.x);
        acc.y = acc.y > 0.f ? acc.y : expm1f(acc.y);
        acc.z = acc.z > 0.f ? acc.z : expm1f(acc.z);
        acc.w = acc.w > 0.f ? acc.w : expm1f(acc.w);
    }
    if (Xo) ((float4*)(Xo + (size_t)v * D))[t] = acc;
    if (Xhi) {
        __nv_bfloat162* ph = (__nv_bfloat162*)(Xhi + (size_t)v * D);
        ph[2 * t]     = __nv_bfloat162(__float2bfloat16(acc.x), __float2bfloat16(acc.y));
        ph[2 * t + 1] = __nv_bfloat162(__float2bfloat16(acc.z), __float2bfloat16(acc.w));
    }
}

// ---------------- attention softmax pieces ----------------
__global__ void k_attn_init(float* __restrict__ gvec, unsigned* __restrict__ menc,
                            float* __restrict__ S, float* __restrict__ logit,
                            int n, const float* __restrict__ bc) {
    int i = blockIdx.x * blockDim.x + threadIdx.x;
    if (i < CDIM) gvec[i] = 0.f;
    if (i < n) logit[i] = bc[0];
    if (i == 0) { *menc = 0u; *S = 0.f; }
}

__global__ void __launch_bounds__(256)
k_maxred(const float* __restrict__ l, int n, unsigned* __restrict__ menc) {
    float m = -INFINITY;
    for (int i = blockIdx.x * blockDim.x + threadIdx.x; i < n; i += gridDim.x * blockDim.x)
        m = fmaxf(m, l[i]);
    __shared__ float red[256];
    red[threadIdx.x] = m;
    __syncthreads();
    for (int s = 128; s > 0; s >>= 1) {
        if (threadIdx.x < s) red[threadIdx.x] = fmaxf(red[threadIdx.x], red[threadIdx.x + s]);
        __syncthreads();
    }
    if (threadIdx.x == 0) atomicMax(menc, fenc(red[0]));
}

__global__ void __launch_bounds__(256)
k_sumexp(const float* __restrict__ l, int n, const unsigned* __restrict__ menc,
         float* __restrict__ S) {
    float m = fdec(*menc);
    float s = 0.f;
    for (int i = blockIdx.x * blockDim.x + threadIdx.x; i < n; i += gridDim.x * blockDim.x)
        s += expf(l[i] - m);
    __shared__ float red[256];
    red[threadIdx.x] = s;
    __syncthreads();
    for (int st = 128; st > 0; st >>= 1) {
        if (threadIdx.x < st) red[threadIdx.x] += red[threadIdx.x + st];
        __syncthreads();
    }
    if (threadIdx.x == 0) atomicAdd(S, red[0]);
}

__global__ void __launch_bounds__(256)
k_wsum(const float* __restrict__ x, const float* __restrict__ l, int n,
       const unsigned* __restrict__ menc, const float* __restrict__ S,
       float* __restrict__ gvec) {
    int c = blockIdx.x * 256 + threadIdx.x;
    float m = fdec(*menc);
    float invS = 1.f / *S;
    float acc = 0.f;
    for (int r = blockIdx.y; r < n; r += gridDim.y)
        acc += expf(l[r] - m) * invS * x[(size_t)r * CDIM + c];
    atomicAdd(&gvec[c], acc);
}

__global__ void k_gemv(const float* __restrict__ v, const float* __restrict__ W,
                       const float* __restrict__ b, float* __restrict__ out,
                       int R, int K) {
    int row = blockIdx.x * (blockDim.x >> 5) + (threadIdx.x >> 5);
    if (row >= R) return;
    int lane = threadIdx.x & 31;
    const float* wr = W + (size_t)row * K;
    float s = 0.f;
    for (int k = lane; k < K; k += 32) s += v[k] * wr[k];
    for (int o = 16; o; o >>= 1) s += __shfl_down_sync(0xffffffffu, s, o);
    if (lane == 0) out[row] = s + b[row];
}

__global__ void __launch_bounds__(256)
k_ln(const float* __restrict__ x, const float* __restrict__ g,
     const float* __restrict__ b, float* __restrict__ out, int D) {
    __shared__ float red[256];
    __shared__ float mu_s, rstd_s;
    float s = 0.f;
    for (int i = threadIdx.x; i < D; i += 256) s += x[i];
    red[threadIdx.x] = s;
    __syncthreads();
    for (int st = 128; st > 0; st >>= 1) {
        if (threadIdx.x < st) red[threadIdx.x] += red[threadIdx.x + st];
        __syncthreads();
    }
    if (threadIdx.x == 0) mu_s = red[0] / (float)D;
    __syncthreads();
    float mu = mu_s;
    float vs = 0.f;
    for (int i = threadIdx.x; i < D; i += 256) {
        float d = x[i] - mu;
        vs += d * d;
    }
    red[threadIdx.x] = vs;
    __syncthreads();
    for (int st = 128; st > 0; st >>= 1) {
        if (threadIdx.x < st) red[threadIdx.x] += red[threadIdx.x + st];
        __syncthreads();
    }
    if (threadIdx.x == 0) rstd_s = rsqrtf(red[0] / (float)D + 1e-5f);
    __syncthreads();
    float rstd = rstd_s;
    for (int i = threadIdx.x; i < D; i += 256)
        out[i] = (x[i] - mu) * rstd * g[i] + b[i];
}

// ---------------- host orchestration ----------------
extern "C" void kernel_launch(void* const* d_in, const int* in_sizes, int n_in,
                              void* d_out, int out_size) {
    // proven-clean footprint: 3 streams + 4 events
    static cudaStream_t st[NB];
    static cudaEvent_t evR, evD[NB];
    static bool inited = false;
    if (!inited) {
        for (int i = 0; i < NB; ++i)
            cudaStreamCreateWithFlags(&st[i], cudaStreamNonBlocking);
        cudaEventCreateWithFlags(&evR, cudaEventDisableTiming);
        for (int i = 0; i < NB; ++i)
            cudaEventCreateWithFlags(&evD[i], cudaEventDisableTiming);
        inited = true;
    }

    float *bufA0, *bufC0, *bufD0, *Y0, *ybuf0, *alpha0, *vm0, *vwinv0, *logits0;
    float *gvec0, *gout0, *gcat, *gcatn, *S0;
    unsigned* menc0;
    int *degE0, *eoff0, *ecur0, *degV0, *voff0, *vcur0, *elist0, *vlist0;
    __nv_bfloat16 *Acthi0, *Actlo0, *Wt0hi, *Wt0lo, *Wt1hi, *Wt1lo, *Wabhi;
    cudaGetSymbolAddress((void**)&bufA0, g_bufA);
    cudaGetSymbolAddress((void**)&bufC0, g_bufC);
    cudaGetSymbolAddress((void**)&bufD0, g_bufD);
    cudaGetSymbolAddress((void**)&Y0, g_Y);
    cudaGetSymbolAddress((void**)&ybuf0, g_ybuf);
    cudaGetSymbolAddress((void**)&alpha0, g_alpha);
    cudaGetSymbolAddress((void**)&vm0, g_vm);
    cudaGetSymbolAddress((void**)&vwinv0, g_vwinv);
    cudaGetSymbolAddress((void**)&logits0, g_logits);
    cudaGetSymbolAddress((void**)&gvec0, g_gvec);
    cudaGetSymbolAddress((void**)&gout0, g_gout);
    cudaGetSymbolAddress((void**)&gcat, g_gcat);
    cudaGetSymbolAddress((void**)&gcatn, g_gcatn);
    cudaGetSymbolAddress((void**)&menc0, g_menc);
    cudaGetSymbolAddress((void**)&S0, g_S);
    cudaGetSymbolAddress((void**)&degE0, g_degE);
    cudaGetSymbolAddress((void**)&eoff0, g_eoff);
    cudaGetSymbolAddress((void**)&ecur0, g_ecur);
    cudaGetSymbolAddress((void**)&degV0, g_degV);
    cudaGetSymbolAddress((void**)&voff0, g_voff);
    cudaGetSymbolAddress((void**)&vcur0, g_vcur);
    cudaGetSymbolAddress((void**)&elist0, g_elist);
    cudaGetSymbolAddress((void**)&vlist0, g_vlist);
    cudaGetSymbolAddress((void**)&Acthi0, g_Acthi);
    cudaGetSymbolAddress((void**)&Actlo0, g_Actlo);
    cudaGetSymbolAddress((void**)&Wt0hi, g_Wt0hi);
    cudaGetSymbolAddress((void**)&Wt0lo, g_Wt0lo);
    cudaGetSymbolAddress((void**)&Wt1hi, g_Wt1hi);
    cudaGetSymbolAddress((void**)&Wt1lo, g_Wt1lo);
    cudaGetSymbolAddress((void**)&Wabhi, g_Wabhi);

    const int GSMEM3 = 81920, GSMEM1 = 40960;
    cudaFuncSetAttribute(k_mma_gemm3, cudaFuncAttributeMaxDynamicSharedMemorySize, GSMEM3);
    cudaFuncSetAttribute(k_mma_logit, cudaFuncAttributeMaxDynamicSharedMemorySize, GSMEM1);

    int xi[3], vii[3], eii[3];
    if (in_sizes[1] == NV * CDIM) {
        for (int b = 0; b < 3; ++b) { xi[b] = b; vii[b] = 3 + 2 * b; eii[b] = 4 + 2 * b; }
    } else {
        for (int b = 0; b < 3; ++b) { xi[b] = 3 * b; vii[b] = 3 * b + 1; eii[b] = 3 * b + 2; }
    }
    const float* Wt0  = (const float*)d_in[9];
    const float* bt0  = (const float*)d_in[10];
    const float* we0  = (const float*)d_in[11];
    const float* Wt1  = (const float*)d_in[12];
    const float* bt1  = (const float*)d_in[13];
    const float* we1  = (const float*)d_in[14];
    const float* Wa   = (const float*)d_in[15];
    const float* ba   = (const float*)d_in[16];
    const float* Wb   = (const float*)d_in[17];
    const float* bb   = (const float*)d_in[18];
    const float* Wc   = (const float*)d_in[19];
    const float* bc   = (const float*)d_in[20];
    const float* Wout = (const float*)d_in[21];
    const float* bout = (const float*)d_in[22];
    const float* gbn  = (const float*)d_in[23];
    const float* bbn  = (const float*)d_in[24];
    const float* gbn2 = (const float*)d_in[25];
    const float* bbn2 = (const float*)d_in[26];
    const float* Wf   = (const float*)d_in[27];
    const float* bf   = (const float*)d_in[28];

    const int EB = (EI + 255) / 256;

    // shared weight prep on the capture stream
    k_split<<<512, 256>>>(Wt0, Wt0hi, Wt0lo, 512 * 1024 / 4);
    k_split<<<512, 256>>>(Wt1, Wt1hi, Wt1lo, 1024 * 512 / 4);
    k_split_inter<<<512, 256>>>(Wa, Wb, Wabhi);

    cudaEventRecord(evR, 0);
    for (int b = 0; b < NB; ++b) cudaStreamWaitEvent(st[b], evR, 0);

    for (int b = 0; b < NB; ++b) {
        cudaStream_t s = st[b];
        const float* X = (const float*)d_in[xi[b]];
        const int* vi = (const int*)d_in[vii[b]];
        const int* ei = (const int*)d_in[eii[b]];

        float* Y1   = bufA0 + (size_t)b * NV * HIDD;     // [ME,512]
        float* h1   = bufC0 + (size_t)b * NV * CDIM;     // [NV,512]
        float* bufD = bufD0 + (size_t)b * NV * CDIM;     // h [NV,1024]
        float* Y2   = Y0    + (size_t)b * ME * CDIM;     // [ME,1024]
        float* ybuf = ybuf0 + (size_t)b * ME * CDIM;     // y [ME,1024]
        float* alpha = alpha0 + (size_t)b * ME;
        float* vm = vm0 + (size_t)b * NV;
        float* vwinv = vwinv0 + (size_t)b * NV;
        float* logits = logits0 + (size_t)b * NV;
        float* gvec = gvec0 + (size_t)b * CDIM;
        float* gout = gout0 + (size_t)b * CDIM;
        unsigned* menc = menc0 + b;
        float* S = S0 + b;
        int* degE = degE0 + (size_t)b * ME;
        int* eoff = eoff0 + (size_t)b * (ME + 1);
        int* ecur = ecur0 + (size_t)b * ME;
        int* degV = degV0 + (size_t)b * NV;
        int* voff = voff0 + (size_t)b * (NV + 1);
        int* vcur = vcur0 + (size_t)b * NV;
        int* elist = elist0 + (size_t)b * EI;
        int* vlist = vlist0 + (size_t)b * EI;
        __nv_bfloat16* Acthi = Acthi0 + (size_t)b * NV * CDIM;
        __nv_bfloat16* Actlo = Actlo0 + (size_t)b * NV * CDIM;

        // ----- CSR -----
        k_zero_csr<<<(NV + 255) / 256, 256, 0, s>>>(degE, degV);
        k_count<<<EB, 256, 0, s>>>(vi, ei, degV, degE);
        k_scan<<<1, 1024, 0, s>>>(degE, eoff, ecur, ME);
        k_scan<<<1, 1024, 0, s>>>(degV, voff, vcur, NV);
        k_fill<<<EB, 256, 0, s>>>(vi, ei, ecur, vcur, elist, vlist);

        // ----- layer 1 (transform commuted past mean-aggregation) -----
        // Xm0 = v2e_mean(X)  -> bf16 hi/lo only [ME,1024]
        k_v2e<CDIM><<<ME, CDIM / 4, 0, s>>>(X, nullptr, Acthi, Actlo, eoff, elist);
        // Y1 = Xm0 @ Wt0^T + bt0*(deg>0)  [ME,512]
        {
            dim3 g(HIDD / 128, (ME + 127) / 128);
            k_mma_gemm3<<<g, 256, GSMEM3, s>>>(Acthi, Actlo, Wt0hi, Wt0lo, bt0, degE,
                                               Y1, ME, HIDD, CDIM);
        }
        k_alpha<HIDD><<<ME, HIDD / 4, 0, s>>>(Y1, we0, alpha);
        k_vstats<<<(NV + 255) / 256, 256, 0, s>>>(alpha, voff, vlist, vm, vwinv);
        k_e2v<HIDD, true><<<NV, HIDD / 4, 0, s>>>(Y1, h1, nullptr,
                                                  voff, vlist, alpha, vm, vwinv);

        // ----- layer 2 -----
        // Xm1 = v2e_mean(h1) -> bf16 hi/lo only [ME,512]
        k_v2e<HIDD><<<ME, HIDD / 4, 0, s>>>(h1, nullptr, Acthi, Actlo, eoff, elist);
        // Y2 = Xm1 @ Wt1^T + bt1*(deg>0)  [ME,1024]
        {
            dim3 g(CDIM / 128, (ME + 127) / 128);
            k_mma_gemm3<<<g, 256, GSMEM3, s>>>(Acthi, Actlo, Wt1hi, Wt1lo, bt1, degE,
                                               Y2, ME, CDIM, HIDD);
        }
        k_alpha<CDIM><<<ME, CDIM / 4, 0, s>>>(Y2, we1, alpha);
        k_vstats<<<(NV + 255) / 256, 256, 0, s>>>(alpha, voff, vlist, vm, vwinv);
        // h = e2v(Y2) [NV,1024] fp32 + bf16 hi for h-attention
        k_e2v<CDIM, false><<<NV, CDIM / 4, 0, s>>>(Y2, bufD, Acthi,
                                                   voff, vlist, alpha, vm, vwinv);

        // ----- y = v2e_mean(h): fp32 + bf16 hi (into Actlo) -----
        k_v2e<CDIM><<<ME, CDIM / 4, 0, s>>>(bufD, ybuf, Actlo, nullptr, eoff, elist);

        // ----- gated attention on h — fused-logit GEMM -----
        k_attn_init<<<(NV + 255) / 256, 256, 0, s>>>(gvec, menc, S, logits, NV, bc);
        {
            dim3 g(512 / 128, (NV + 127) / 128);
            k_mma_logit<<<g, 256, GSMEM1, s>>>(Acthi, Wabhi, ba, bb, Wc, logits, NV, CDIM);
        }
        k_maxred<<<40, 256, 0, s>>>(logits, NV, menc);
        k_sumexp<<<40, 256, 0, s>>>(logits, NV, menc, S);
        {
            dim3 g(CDIM / 256, 125);
            k_wsum<<<g, 256, 0, s>>>(bufD, logits, NV, menc, S, gvec);
        }
        k_gemv<<<128, 256, 0, s>>>(gvec, Wout, bout, gout, CDIM, CDIM);
        k_ln<<<1, 256, 0, s>>>(gout, gbn, bbn, gcat + (size_t)b * CDIM, CDIM);

        // ----- gated attention on y — fused-logit GEMM -----
        k_attn_init<<<(NV + 255) / 256, 256, 0, s>>>(gvec, menc, S, logits, ME, bc);
        {
            dim3 g(512 / 128, (ME + 127) / 128);
            k_mma_logit<<<g, 256, GSMEM1, s>>>(Actlo, Wabhi, ba, bb, Wc, logits, ME, CDIM);
        }
        k_maxred<<<20, 256, 0, s>>>(logits, ME, menc);
        k_sumexp<<<20, 256, 0, s>>>(logits, ME, menc, S);
        {
            dim3 g(CDIM / 256, 125);
            k_wsum<<<g, 256, 0, s>>>(ybuf, logits, ME, menc, S, gvec);
        }
        k_gemv<<<128, 256, 0, s>>>(gvec, Wout, bout, gout, CDIM, CDIM);
        k_ln<<<1, 256, 0, s>>>(gout, gbn, bbn, gcat + (size_t)(3 + b) * CDIM, CDIM);

        cudaEventRecord(evD[b], s);
    }

    for (int b = 0; b < NB; ++b) cudaStreamWaitEvent(0, evD[b], 0);

    k_ln<<<1, 256>>>(gcat, gbn2, bbn2, gcatn, 6 * CDIM);
    k_gemv<<<2, 256>>>(gcatn, Wf, bf, (float*)d_out, 10, 6 * CDIM);
}